// round 13
// baseline (speedup 1.0000x reference)
#include <cuda_runtime.h>
#include <cuda_bf16.h>
#include <math.h>
#include <stdint.h>

#define B_   8
#define T_   2048
#define DM_  256
#define HID_ 1024
#define ROWS (B_ * T_)   // 16384

// ---------------- scratch (static device globals; no allocation) ----------------
__device__ float g_v   [ROWS * DM_];
__device__ float g_a   [ROWS * DM_];
__device__ float g_actx[ROWS * DM_];
__device__ float g_x   [ROWS * 3 * DM_];   // tf32-rounded
__device__ float g_logit[ROWS];

// transposed weights, tf32-rounded fp32: [N, K] K-major
__device__ float g_wvt[DM_ * 1024];
__device__ float g_wat[DM_ * 768];
__device__ float g_w1t[HID_ * 768];

// ------------------------------- helpers ----------------------------------------
__device__ __forceinline__ uint32_t smem_u32(const void* p) {
    uint32_t a;
    asm("{ .reg .u64 t; cvta.to.shared.u64 t, %1; cvt.u32.u64 %0, t; }"
        : "=r"(a) : "l"(p));
    return a;
}

__device__ __forceinline__ void ldm4(uint32_t r[4], uint32_t addr) {
    asm volatile("ldmatrix.sync.aligned.m8n8.x4.shared.b16 {%0,%1,%2,%3}, [%4];"
        : "=r"(r[0]), "=r"(r[1]), "=r"(r[2]), "=r"(r[3]) : "r"(addr));
}

__device__ __forceinline__ void mma_tf32(float d[4], const uint32_t a[4],
                                         const uint32_t b0, const uint32_t b1) {
    asm volatile(
        "mma.sync.aligned.m16n8k8.row.col.f32.tf32.tf32.f32 "
        "{%0,%1,%2,%3}, {%4,%5,%6,%7}, {%8,%9}, {%0,%1,%2,%3};"
        : "+f"(d[0]), "+f"(d[1]), "+f"(d[2]), "+f"(d[3])
        : "r"(a[0]), "r"(a[1]), "r"(a[2]), "r"(a[3]), "r"(b0), "r"(b1));
}

__device__ __forceinline__ void cvt_tf32(uint32_t& r) {
    asm("cvt.rna.tf32.f32 %0, %0;" : "+r"(r));
}
__device__ __forceinline__ float round_tf32(float x) {
    uint32_t u = __float_as_uint(x);
    cvt_tf32(u);
    return __uint_as_float(u);
}

__device__ __forceinline__ void cp16(uint32_t dst, const void* src) {
    asm volatile("cp.async.cg.shared.global [%0], [%1], 16;"
                 :: "r"(dst), "l"(src) : "memory");
}
__device__ __forceinline__ void cp_commit() {
    asm volatile("cp.async.commit_group;" ::: "memory");
}
__device__ __forceinline__ void cp_wait2() {
    asm volatile("cp.async.wait_group 2;" ::: "memory");
}

// ------ weight prep: transpose + tf32 round: out[N,K] (fp32 storage) ------------
__global__ void wprep_kernel(const float* __restrict__ W,
                             float* __restrict__ ot, int K, int N)
{
    __shared__ float t[32][33];
    int k0 = blockIdx.y * 32, n0 = blockIdx.x * 32;
    int x = threadIdx.x, y = threadIdx.y;   // 32 x 8
#pragma unroll
    for (int r = 0; r < 32; r += 8)
        t[y + r][x] = W[(size_t)(k0 + y + r) * N + n0 + x];
    __syncthreads();
#pragma unroll
    for (int r = 0; r < 32; r += 8)
        ot[(size_t)(n0 + y + r) * K + k0 + x] = round_tf32(t[x][y + r]);
}

// ------------- TF32 HMMA GEMM: 4-stage cp.async + B-fragment pipelining ---------
// A [M,K] fp32 row-major; Bt [N,K] tf32 K-major. 512 thr / 16 warps,
// CTA tile 128x256, warp tile 32x64, BK=32 (128B rows, XOR-8 swizzle), 4 stages.
// Inner loop flattened over 16 (ks,nf2) steps with double-buffered B fragments.
// EPI: 2 = bias + LayerNorm over N==256, store C.
//      3 = bias + exact GELU + dot with w2, atomicAdd into logit[row]; no C.
// CVTA: round A fragments to tf32 in-kernel (0 if A pre-rounded in gmem).
template <int EPI, int CVTA>
__global__ __launch_bounds__(512, 1)
void gemm_mma(const float* __restrict__ A,
              const float* __restrict__ Bt,
              const float* __restrict__ bias,
              float* __restrict__ C,
              const float* __restrict__ w2,
              float* __restrict__ logit,
              int N, int K)
{
    extern __shared__ char smem[];
    constexpr int R_B   = 16384;
    constexpr int STAGE = 49152;

    const int tid = threadIdx.x, wid = tid >> 5, lane = tid & 31;
    const int wm = wid & 3, wn = wid >> 2;
    const int row0 = blockIdx.y * 128, col0 = blockIdx.x * 256;
    const uint32_t sb = smem_u32(smem);

    float acc[2][8][4];
#pragma unroll
    for (int i = 0; i < 2; i++)
#pragma unroll
        for (int j = 0; j < 8; j++)
#pragma unroll
            for (int q = 0; q < 4; q++) acc[i][j][q] = 0.f;

    const int ph = lane >> 4;
    uint32_t rdA[2], rdB[4];
#pragma unroll
    for (int mf = 0; mf < 2; mf++) {
        int r = wm * 32 + mf * 16 + (lane & 15);
        rdA[mf] = sb + (uint32_t)(r * 128 + ((ph ^ (r & 7)) << 4));
    }
#pragma unroll
    for (int nf2 = 0; nf2 < 4; nf2++) {
        int r = wn * 64 + nf2 * 16 + (lane & 15);
        rdB[nf2] = sb + R_B + (uint32_t)(r * 128 + ((ph ^ (r & 7)) << 4));
    }

    const int ar  = tid >> 2;
    const int ac0 = (tid & 3) * 2;
    uint32_t wrA = sb + (uint32_t)(ar * 128 + ((ac0 ^ (ar & 7)) << 4));
    const int br  = tid >> 1;
    const int bc0 = (tid & 1) * 4;
    uint32_t wrB = sb + R_B + (uint32_t)(br * 128 + ((bc0 ^ (br & 7)) << 4));

    const char* pA = (const char*)(A + (size_t)(row0 + ar) * K + ac0 * 4);
    const char* pB = (const char*)(Bt + (size_t)(col0 + br) * K + bc0 * 4);

    auto issue = [&](int k0) {
        size_t off = (size_t)k0 * 4;
        cp16(wrA,       pA + off);
        cp16(wrA ^ 16u, pA + off + 16);
#pragma unroll
        for (int j = 0; j < 4; j++)
            cp16(wrB ^ (uint32_t)(j << 4), pB + off + j * 16);
    };

    const int nc = K >> 5;
#pragma unroll
    for (int s = 0; s < 3; s++) {
        issue(s << 5);
        cp_commit();
        wrA += STAGE; wrB += STAGE;
    }

    for (int c = 0; c < nc; c++) {
        cp_wait2();
        __syncthreads();

        if (c + 3 < nc) issue((c + 3) << 5);
        cp_commit();
        {
            const int wd = (((c + 3) & 3) == 3) ? -3 * STAGE : STAGE;
            wrA += wd; wrB += wd;
        }

        // flattened 16-step inner loop, B fragments double-buffered
        uint32_t tN[4];
        ldm4(tN, rdB[0]);                         // (ks=0, nf2=0)
#pragma unroll
        for (int ks = 0; ks < 4; ks++) {
            const uint32_t kx = (uint32_t)(ks << 5);
            uint32_t a[2][4];
            ldm4(a[0], rdA[0] ^ kx);
            ldm4(a[1], rdA[1] ^ kx);
            if (CVTA) {
#pragma unroll
                for (int mf = 0; mf < 2; mf++)
#pragma unroll
                    for (int q = 0; q < 4; q++) cvt_tf32(a[mf][q]);
            }
#pragma unroll
            for (int nf2 = 0; nf2 < 4; nf2++) {
                uint32_t tC[4] = {tN[0], tN[1], tN[2], tN[3]};
                const int ni = ks * 4 + nf2 + 1;  // next step
                if (ni < 16)
                    ldm4(tN, rdB[ni & 3] ^ (uint32_t)((ni >> 2) << 5));
#pragma unroll
                for (int mf = 0; mf < 2; mf++) {
                    mma_tf32(acc[mf][2 * nf2],     a[mf], tC[0], tC[2]);
                    mma_tf32(acc[mf][2 * nf2 + 1], a[mf], tC[1], tC[3]);
                }
            }
        }

        {
            const int rd = ((c & 3) == 3) ? -3 * STAGE : STAGE;
            rdA[0] += rd; rdA[1] += rd;
#pragma unroll
            for (int i = 0; i < 4; i++) rdB[i] += rd;
        }
    }

    // ------------------------------- epilogue -----------------------------------
    __syncthreads();
    const int r4 = lane >> 2, c2 = (lane & 3) * 2;
    float2 bs[8];
#pragma unroll
    for (int nf = 0; nf < 8; nf++)
        bs[nf] = *(const float2*)&bias[col0 + wn * 64 + nf * 8 + c2];

    if (EPI == 3) {
        float2 ws[8];
#pragma unroll
        for (int nf = 0; nf < 8; nf++)
            ws[nf] = *(const float2*)&w2[col0 + wn * 64 + nf * 8 + c2];
#pragma unroll
        for (int mf = 0; mf < 2; mf++)
#pragma unroll
            for (int h = 0; h < 2; h++) {
                float s = 0.f;
#pragma unroll
                for (int nf = 0; nf < 8; nf++) {
                    float v0 = acc[mf][nf][2 * h]     + bs[nf].x;
                    float v1 = acc[mf][nf][2 * h + 1] + bs[nf].y;
                    v0 = 0.5f * v0 * (1.0f + erff(v0 * 0.70710678118654752f));
                    v1 = 0.5f * v1 * (1.0f + erff(v1 * 0.70710678118654752f));
                    s += v0 * ws[nf].x + v1 * ws[nf].y;
                }
                s += __shfl_xor_sync(0xffffffffu, s, 1);
                s += __shfl_xor_sync(0xffffffffu, s, 2);
                if ((lane & 3) == 0) {
                    int row = row0 + wm * 32 + mf * 16 + h * 8 + r4;
                    atomicAdd(&logit[row], s);
                }
            }
        return;
    }

    // EPI == 2: LayerNorm over 256 cols, store C
    float mu[2][2], inv[2][2];
    {
        float2* part = (float2*)(smem + 4 * STAGE);  // [128][4]
#pragma unroll
        for (int mf = 0; mf < 2; mf++)
#pragma unroll
            for (int h = 0; h < 2; h++) {
                float s1 = 0.f, s2 = 0.f;
#pragma unroll
                for (int nf = 0; nf < 8; nf++) {
                    float v0 = acc[mf][nf][2 * h]     + bs[nf].x;
                    float v1 = acc[mf][nf][2 * h + 1] + bs[nf].y;
                    s1 += v0 + v1; s2 += v0 * v0 + v1 * v1;
                }
                s1 += __shfl_xor_sync(0xffffffffu, s1, 1);
                s2 += __shfl_xor_sync(0xffffffffu, s2, 1);
                s1 += __shfl_xor_sync(0xffffffffu, s1, 2);
                s2 += __shfl_xor_sync(0xffffffffu, s2, 2);
                int rt = wm * 32 + mf * 16 + h * 8 + r4;
                if ((lane & 3) == 0) part[rt * 4 + wn] = make_float2(s1, s2);
            }
        __syncthreads();
#pragma unroll
        for (int mf = 0; mf < 2; mf++)
#pragma unroll
            for (int h = 0; h < 2; h++) {
                int rt = wm * 32 + mf * 16 + h * 8 + r4;
                float s1 = 0.f, s2 = 0.f;
#pragma unroll
                for (int w = 0; w < 4; w++) {
                    float2 p = part[rt * 4 + w];
                    s1 += p.x; s2 += p.y;
                }
                float m = s1 * (1.0f / 256.0f);
                float var = s2 * (1.0f / 256.0f) - m * m;
                mu[mf][h] = m;
                inv[mf][h] = rsqrtf(var + 1e-5f);
            }
    }

#pragma unroll
    for (int mf = 0; mf < 2; mf++)
#pragma unroll
        for (int h = 0; h < 2; h++) {
            int row = row0 + wm * 32 + mf * 16 + h * 8 + r4;
#pragma unroll
            for (int nf = 0; nf < 8; nf++) {
                float v0 = (acc[mf][nf][2 * h]     + bs[nf].x - mu[mf][h]) * inv[mf][h];
                float v1 = (acc[mf][nf][2 * h + 1] + bs[nf].y - mu[mf][h]) * inv[mf][h];
                int col = col0 + wn * 64 + nf * 8 + c2;
                *(float2*)&C[(size_t)row * N + col] = make_float2(v0, v1);
            }
        }
}

// -------- fused fractional shift + causal window context: g_actx from g_a -------
__global__ void ctx_kernel(const float* __restrict__ theta)
{
    const int t = blockIdx.x;
    const int b = blockIdx.y;
    const int d = threadIdx.x;

    float th    = fminf(fmaxf(theta[0], -12.f), 12.f);
    float delta = 2.0f + 4.0f / (1.0f + expf(-th));
    float dl    = fminf(fmaxf(delta, 0.f), (float)(T_ - 1));
    float nf    = floorf(dl);
    float alpha = dl - nf;
    int   ni    = (int)nf;

    float center = fminf(fmaxf((float)t + delta, 0.f), (float)t);
    int lo = max(0, (int)floorf(center - 5.0f) - 1);
    int hi = min(t, (int)ceilf (center + 5.0f) + 1);

    const float* ab = g_a + (size_t)b * T_ * DM_;
    float sum = 0.f; int cnt = 0;
    for (int tau = lo; tau <= hi; tau++) {
        if (fabsf((float)tau - center) <= 5.0f) {
            cnt++;
            int i0 = min(max(tau - ni, 0), T_ - 1);
            int i1 = min(i0 + 1, T_ - 1);
            sum += (1.0f - alpha) * ab[i0 * DM_ + d] + alpha * ab[i1 * DM_ + d];
        }
    }
    g_actx[((size_t)b * T_ + t) * DM_ + d] = sum / fmaxf((float)cnt, 1e-8f);
}

// -- build X = [an, vn, an*vn] tf32-rounded, with L2 normalization (warp/row) ----
__global__ void buildx_kernel()
{
    const int row  = blockIdx.x * 8 + (threadIdx.x >> 5);
    const int lane = threadIdx.x & 31;
    const float* v  = g_v    + (size_t)row * DM_;
    const float* ac = g_actx + (size_t)row * DM_;

    float vv[8], aa[8];
    float sv = 0.f, sa = 0.f;
#pragma unroll
    for (int i = 0; i < 8; i++) {
        vv[i] = v[lane + 32 * i];
        aa[i] = ac[lane + 32 * i];
        sv += vv[i] * vv[i];
        sa += aa[i] * aa[i];
    }
#pragma unroll
    for (int o = 16; o > 0; o >>= 1) {
        sv += __shfl_xor_sync(0xffffffffu, sv, o);
        sa += __shfl_xor_sync(0xffffffffu, sa, o);
    }
    float iv = 1.0f / fmaxf(sqrtf(sv), 1e-8f);
    float ia = 1.0f / fmaxf(sqrtf(sa), 1e-8f);

    float* x = g_x + (size_t)row * (3 * DM_);
#pragma unroll
    for (int i = 0; i < 8; i++) {
        int d = lane + 32 * i;
        float an = aa[i] * ia, vn = vv[i] * iv;
        x[d]           = round_tf32(an);
        x[DM_ + d]     = round_tf32(vn);
        x[2 * DM_ + d] = round_tf32(an * vn);
    }
}

// -------- gate: logit -> sigmoid -> blend: out = g*a_ctx + (1-g)*v --------------
__global__ void gate_kernel(const float* __restrict__ b2, float* __restrict__ out)
{
    const int row = blockIdx.x;
    const int tid = threadIdx.x;
    float logitv = fminf(fmaxf(g_logit[row] + b2[0], -12.f), 12.f);
    float g = 1.0f / (1.0f + expf(-logitv));
    g = fminf(fmaxf(g, 0.05f), 0.95f);
    float ac = g_actx[(size_t)row * DM_ + tid];
    float v  = g_v  [(size_t)row * DM_ + tid];
    out[(size_t)row * DM_ + tid] = g * ac + (1.0f - g) * v;
}

// --------------------------------- launcher ------------------------------------
extern "C" void kernel_launch(void* const* d_in, const int* in_sizes, int n_in,
                              void* d_out, int out_size)
{
    const float* video = (const float*)d_in[0];
    const float* audio = (const float*)d_in[1];
    const float* Wv    = (const float*)d_in[2];
    const float* bv    = (const float*)d_in[3];
    const float* Wa    = (const float*)d_in[4];
    const float* ba    = (const float*)d_in[5];
    const float* theta = (const float*)d_in[6];
    const float* W1    = (const float*)d_in[7];
    const float* b1    = (const float*)d_in[8];
    const float* W2    = (const float*)d_in[9];
    const float* b2    = (const float*)d_in[10];
    float* out = (float*)d_out;

    float *pv, *pa, *px, *plog, *wvt, *wat, *w1t;
    cudaGetSymbolAddress((void**)&pv,   g_v);
    cudaGetSymbolAddress((void**)&pa,   g_a);
    cudaGetSymbolAddress((void**)&px,   g_x);
    cudaGetSymbolAddress((void**)&plog, g_logit);
    cudaGetSymbolAddress((void**)&wvt,  g_wvt);
    cudaGetSymbolAddress((void**)&wat,  g_wat);
    cudaGetSymbolAddress((void**)&w1t,  g_w1t);

    const int SMEM = 4 * 49152 + 128 * 4 * 8;   // 200704
    cudaFuncSetAttribute((const void*)gemm_mma<2, 1>,
                         cudaFuncAttributeMaxDynamicSharedMemorySize, SMEM);
    cudaFuncSetAttribute((const void*)gemm_mma<3, 0>,
                         cudaFuncAttributeMaxDynamicSharedMemorySize, SMEM);

    cudaMemsetAsync(plog, 0, ROWS * sizeof(float));

    dim3 wblk(32, 8);
    wprep_kernel<<<dim3(DM_  / 32, 1024 / 32), wblk>>>(Wv, wvt, 1024, DM_);
    wprep_kernel<<<dim3(DM_  / 32,  768 / 32), wblk>>>(Wa, wat,  768, DM_);
    wprep_kernel<<<dim3(HID_ / 32,  768 / 32), wblk>>>(W1, w1t,  768, HID_);

    // v = LN(video @ Wv + bv)   M=16384 K=1024 N=256
    gemm_mma<2, 1><<<dim3(1, ROWS / 128), dim3(512), SMEM>>>(video, wvt, bv, pv,
                                                             nullptr, nullptr, DM_, 1024);
    // a = LN(audio @ Wa + ba)   M=16384 K=768  N=256
    gemm_mma<2, 1><<<dim3(1, ROWS / 128), dim3(512), SMEM>>>(audio, wat, ba, pa,
                                                             nullptr, nullptr, DM_, 768);
    // a_ctx
    ctx_kernel<<<dim3(T_, B_), dim3(256)>>>(theta);
    // X = [an, vn, an*vn] (tf32-rounded)
    buildx_kernel<<<ROWS / 8, dim3(256)>>>();
    // logits += gelu(X @ W1 + b1) . W2
    gemm_mma<3, 0><<<dim3(HID_ / 256, ROWS / 128), dim3(512), SMEM>>>(px, w1t, b1, nullptr,
                                                                      W2, plog, HID_, 768);
    // gate + blend
    gate_kernel<<<ROWS, dim3(256)>>>(b2, out);
}

// round 14
// speedup vs baseline: 1.0228x; 1.0228x over previous
#include <cuda_runtime.h>
#include <cuda_bf16.h>
#include <math.h>
#include <stdint.h>

#define B_   8
#define T_   2048
#define DM_  256
#define HID_ 1024
#define ROWS (B_ * T_)   // 16384

// ---------------- scratch (static device globals; no allocation) ----------------
__device__ float g_v   [ROWS * DM_];
__device__ float g_a   [ROWS * DM_];
__device__ float g_actx[ROWS * DM_];
__device__ float g_x   [ROWS * 3 * DM_];   // tf32-rounded
__device__ float g_logit[ROWS];

// transposed weights, tf32-rounded fp32: [N, K] K-major
__device__ float g_wvt[DM_ * 1024];
__device__ float g_wat[DM_ * 768];
__device__ float g_w1t[HID_ * 768];

// ------------------------------- helpers ----------------------------------------
__device__ __forceinline__ uint32_t smem_u32(const void* p) {
    uint32_t a;
    asm("{ .reg .u64 t; cvta.to.shared.u64 t, %1; cvt.u32.u64 %0, t; }"
        : "=r"(a) : "l"(p));
    return a;
}

__device__ __forceinline__ void ldm4(uint32_t r[4], uint32_t addr) {
    asm volatile("ldmatrix.sync.aligned.m8n8.x4.shared.b16 {%0,%1,%2,%3}, [%4];"
        : "=r"(r[0]), "=r"(r[1]), "=r"(r[2]), "=r"(r[3]) : "r"(addr));
}

__device__ __forceinline__ void mma_tf32(float d[4], const uint32_t a[4],
                                         const uint32_t b0, const uint32_t b1) {
    asm volatile(
        "mma.sync.aligned.m16n8k8.row.col.f32.tf32.tf32.f32 "
        "{%0,%1,%2,%3}, {%4,%5,%6,%7}, {%8,%9}, {%0,%1,%2,%3};"
        : "+f"(d[0]), "+f"(d[1]), "+f"(d[2]), "+f"(d[3])
        : "r"(a[0]), "r"(a[1]), "r"(a[2]), "r"(a[3]), "r"(b0), "r"(b1));
}

__device__ __forceinline__ void cvt_tf32(uint32_t& r) {
    asm("cvt.rna.tf32.f32 %0, %0;" : "+r"(r));
}
__device__ __forceinline__ float round_tf32(float x) {
    uint32_t u = __float_as_uint(x);
    cvt_tf32(u);
    return __uint_as_float(u);
}

__device__ __forceinline__ void cp16(uint32_t dst, const void* src) {
    asm volatile("cp.async.cg.shared.global [%0], [%1], 16;"
                 :: "r"(dst), "l"(src) : "memory");
}
__device__ __forceinline__ void cp_commit() {
    asm volatile("cp.async.commit_group;" ::: "memory");
}
__device__ __forceinline__ void cp_wait2() {
    asm volatile("cp.async.wait_group 2;" ::: "memory");
}
__device__ __forceinline__ void cp_wait1() {
    asm volatile("cp.async.wait_group 1;" ::: "memory");
}

// ------ weight prep: transpose + tf32 round: out[N,K] (fp32 storage) ------------
__global__ void wprep_kernel(const float* __restrict__ W,
                             float* __restrict__ ot, int K, int N)
{
    __shared__ float t[32][33];
    int k0 = blockIdx.y * 32, n0 = blockIdx.x * 32;
    int x = threadIdx.x, y = threadIdx.y;   // 32 x 8
#pragma unroll
    for (int r = 0; r < 32; r += 8)
        t[y + r][x] = W[(size_t)(k0 + y + r) * N + n0 + x];
    __syncthreads();
#pragma unroll
    for (int r = 0; r < 32; r += 8)
        ot[(size_t)(n0 + y + r) * K + k0 + x] = round_tf32(t[x][y + r]);
}

// ------------- LN GEMM: TF32 HMMA, 4-stage cp.async (R10 proven config) ---------
// A [M,K] fp32 row-major (tf32-rounded in-kernel); Bt [N,K] tf32 K-major.
// 512 thr / 16 warps, CTA tile 128x256, warp tile 32x64, BK=32, 4 stages.
// Epilogue: bias + LayerNorm over N==256, store C.
__global__ __launch_bounds__(512, 1)
void gemm_ln(const float* __restrict__ A,
             const float* __restrict__ Bt,
             const float* __restrict__ bias,
             float* __restrict__ C,
             int N, int K)
{
    extern __shared__ char smem[];
    constexpr int R_B   = 16384;
    constexpr int STAGE = 49152;

    const int tid = threadIdx.x, wid = tid >> 5, lane = tid & 31;
    const int wm = wid & 3, wn = wid >> 2;
    const int row0 = blockIdx.y * 128, col0 = blockIdx.x * 256;
    const uint32_t sb = smem_u32(smem);

    float acc[2][8][4];
#pragma unroll
    for (int i = 0; i < 2; i++)
#pragma unroll
        for (int j = 0; j < 8; j++)
#pragma unroll
            for (int q = 0; q < 4; q++) acc[i][j][q] = 0.f;

    const int ph = lane >> 4;
    uint32_t rdA[2], rdB[4];
#pragma unroll
    for (int mf = 0; mf < 2; mf++) {
        int r = wm * 32 + mf * 16 + (lane & 15);
        rdA[mf] = sb + (uint32_t)(r * 128 + ((ph ^ (r & 7)) << 4));
    }
#pragma unroll
    for (int nf2 = 0; nf2 < 4; nf2++) {
        int r = wn * 64 + nf2 * 16 + (lane & 15);
        rdB[nf2] = sb + R_B + (uint32_t)(r * 128 + ((ph ^ (r & 7)) << 4));
    }

    const int ar  = tid >> 2;
    const int ac0 = (tid & 3) * 2;
    uint32_t wrA = sb + (uint32_t)(ar * 128 + ((ac0 ^ (ar & 7)) << 4));
    const int br  = tid >> 1;
    const int bc0 = (tid & 1) * 4;
    uint32_t wrB = sb + R_B + (uint32_t)(br * 128 + ((bc0 ^ (br & 7)) << 4));

    const char* pA = (const char*)(A + (size_t)(row0 + ar) * K + ac0 * 4);
    const char* pB = (const char*)(Bt + (size_t)(col0 + br) * K + bc0 * 4);

    auto issue = [&](int k0) {
        size_t off = (size_t)k0 * 4;
        cp16(wrA,       pA + off);
        cp16(wrA ^ 16u, pA + off + 16);
#pragma unroll
        for (int j = 0; j < 4; j++)
            cp16(wrB ^ (uint32_t)(j << 4), pB + off + j * 16);
    };

    const int nc = K >> 5;
#pragma unroll
    for (int s = 0; s < 3; s++) {
        issue(s << 5);
        cp_commit();
        wrA += STAGE; wrB += STAGE;
    }

    for (int c = 0; c < nc; c++) {
        cp_wait2();
        __syncthreads();

        if (c + 3 < nc) issue((c + 3) << 5);
        cp_commit();
        {
            const int wd = (((c + 3) & 3) == 3) ? -3 * STAGE : STAGE;
            wrA += wd; wrB += wd;
        }

#pragma unroll
        for (int ks = 0; ks < 4; ks++) {
            const uint32_t kx = (uint32_t)(ks << 5);
            uint32_t a[2][4];
            ldm4(a[0], rdA[0] ^ kx);
            ldm4(a[1], rdA[1] ^ kx);
#pragma unroll
            for (int mf = 0; mf < 2; mf++)
#pragma unroll
                for (int q = 0; q < 4; q++) cvt_tf32(a[mf][q]);
#pragma unroll
            for (int nf2 = 0; nf2 < 4; nf2++) {
                uint32_t t[4];
                ldm4(t, rdB[nf2] ^ kx);
#pragma unroll
                for (int mf = 0; mf < 2; mf++) {
                    mma_tf32(acc[mf][2 * nf2],     a[mf], t[0], t[2]);
                    mma_tf32(acc[mf][2 * nf2 + 1], a[mf], t[1], t[3]);
                }
            }
        }

        {
            const int rd = ((c & 3) == 3) ? -3 * STAGE : STAGE;
            rdA[0] += rd; rdA[1] += rd;
#pragma unroll
            for (int i = 0; i < 4; i++) rdB[i] += rd;
        }
    }

    // epilogue: bias + LayerNorm over 256 cols, store C
    __syncthreads();
    const int r4 = lane >> 2, c2 = (lane & 3) * 2;
    float2 bs[8];
#pragma unroll
    for (int nf = 0; nf < 8; nf++)
        bs[nf] = *(const float2*)&bias[col0 + wn * 64 + nf * 8 + c2];

    float mu[2][2], inv[2][2];
    {
        float2* part = (float2*)(smem + 4 * STAGE);  // [128][4]
#pragma unroll
        for (int mf = 0; mf < 2; mf++)
#pragma unroll
            for (int h = 0; h < 2; h++) {
                float s1 = 0.f, s2 = 0.f;
#pragma unroll
                for (int nf = 0; nf < 8; nf++) {
                    float v0 = acc[mf][nf][2 * h]     + bs[nf].x;
                    float v1 = acc[mf][nf][2 * h + 1] + bs[nf].y;
                    s1 += v0 + v1; s2 += v0 * v0 + v1 * v1;
                }
                s1 += __shfl_xor_sync(0xffffffffu, s1, 1);
                s2 += __shfl_xor_sync(0xffffffffu, s2, 1);
                s1 += __shfl_xor_sync(0xffffffffu, s1, 2);
                s2 += __shfl_xor_sync(0xffffffffu, s2, 2);
                int rt = wm * 32 + mf * 16 + h * 8 + r4;
                if ((lane & 3) == 0) part[rt * 4 + wn] = make_float2(s1, s2);
            }
        __syncthreads();
#pragma unroll
        for (int mf = 0; mf < 2; mf++)
#pragma unroll
            for (int h = 0; h < 2; h++) {
                int rt = wm * 32 + mf * 16 + h * 8 + r4;
                float s1 = 0.f, s2 = 0.f;
#pragma unroll
                for (int w = 0; w < 4; w++) {
                    float2 p = part[rt * 4 + w];
                    s1 += p.x; s2 += p.y;
                }
                float m = s1 * (1.0f / 256.0f);
                float var = s2 * (1.0f / 256.0f) - m * m;
                mu[mf][h] = m;
                inv[mf][h] = rsqrtf(var + 1e-5f);
            }
    }

#pragma unroll
    for (int mf = 0; mf < 2; mf++)
#pragma unroll
        for (int h = 0; h < 2; h++) {
            int row = row0 + wm * 32 + mf * 16 + h * 8 + r4;
#pragma unroll
            for (int nf = 0; nf < 8; nf++) {
                float v0 = (acc[mf][nf][2 * h]     + bs[nf].x - mu[mf][h]) * inv[mf][h];
                float v1 = (acc[mf][nf][2 * h + 1] + bs[nf].y - mu[mf][h]) * inv[mf][h];
                int col = col0 + wn * 64 + nf * 8 + c2;
                *(float2*)&C[(size_t)row * N + col] = make_float2(v0, v1);
            }
        }
}

// ------------- MLP GEMM: 2 CTAs/SM, 256 thr, BM=128 BN=128, warp tile 32x64 -----
// Same per-warp structure as the LN kernel (MMA:ldsm ratio preserved); smaller
// CTA so two coexist per SM and their barrier phases interleave. 3-stage
// cp.async. A = g_x pre-rounded tf32 (no cvt). Epilogue: bias + exact GELU +
// dot(w2) -> atomicAdd logit[row].
__global__ __launch_bounds__(256, 2)
void gemm_mlp(const float* __restrict__ A,
              const float* __restrict__ Bt,
              const float* __restrict__ bias,
              const float* __restrict__ w2,
              float* __restrict__ logit,
              int K)
{
    extern __shared__ char smem[];
    constexpr int R_B   = 16384;             // A: 128 rows x 128B
    constexpr int STAGE = 32768;             // A 16KB + B 16KB

    const int tid = threadIdx.x, wid = tid >> 5, lane = tid & 31;
    const int wm = wid & 3, wn = wid >> 2;   // warp grid 4 (M) x 2 (N)
    const int row0 = blockIdx.y * 128, col0 = blockIdx.x * 128;
    const uint32_t sb = smem_u32(smem);

    float acc[2][8][4];
#pragma unroll
    for (int i = 0; i < 2; i++)
#pragma unroll
        for (int j = 0; j < 8; j++)
#pragma unroll
            for (int q = 0; q < 4; q++) acc[i][j][q] = 0.f;

    const int ph = lane >> 4;
    uint32_t rdA[2], rdB[4];
#pragma unroll
    for (int mf = 0; mf < 2; mf++) {
        int r = wm * 32 + mf * 16 + (lane & 15);
        rdA[mf] = sb + (uint32_t)(r * 128 + ((ph ^ (r & 7)) << 4));
    }
#pragma unroll
    for (int nf2 = 0; nf2 < 4; nf2++) {
        int r = wn * 64 + nf2 * 16 + (lane & 15);
        rdB[nf2] = sb + R_B + (uint32_t)(r * 128 + ((ph ^ (r & 7)) << 4));
    }

    // staging: A 128 rows, 2 thr/row x 4 chunks; B 128 rows, 2 thr/row x 4 chunks
    const int ar  = tid >> 1;
    const int ac0 = (tid & 1) * 4;
    uint32_t wrA = sb + (uint32_t)(ar * 128 + ((ac0 ^ (ar & 7)) << 4));
    uint32_t wrB = wrA + R_B;

    const char* pA = (const char*)(A + (size_t)(row0 + ar) * K + ac0 * 4);
    const char* pB = (const char*)(Bt + (size_t)(col0 + ar) * K + ac0 * 4);

    auto issue = [&](int k0) {
        size_t off = (size_t)k0 * 4;
#pragma unroll
        for (int j = 0; j < 4; j++) {
            cp16(wrA ^ (uint32_t)(j << 4), pA + off + j * 16);
            cp16(wrB ^ (uint32_t)(j << 4), pB + off + j * 16);
        }
    };

    const int nc = K >> 5;
#pragma unroll
    for (int s = 0; s < 2; s++) {
        issue(s << 5);
        cp_commit();
        wrA += STAGE; wrB += STAGE;          // now at stage 2
    }

    for (int c = 0; c < nc; c++) {
        cp_wait1();
        __syncthreads();

        if (c + 2 < nc) issue((c + 2) << 5);
        cp_commit();
        {   // write stage (c+2)%3 -> (c+3)%3
            const int wd = (((c + 2) % 3) == 2) ? -2 * STAGE : STAGE;
            wrA += wd; wrB += wd;
        }

#pragma unroll
        for (int ks = 0; ks < 4; ks++) {
            const uint32_t kx = (uint32_t)(ks << 5);
            uint32_t a[2][4];
            ldm4(a[0], rdA[0] ^ kx);
            ldm4(a[1], rdA[1] ^ kx);
#pragma unroll
            for (int nf2 = 0; nf2 < 4; nf2++) {
                uint32_t t[4];
                ldm4(t, rdB[nf2] ^ kx);
#pragma unroll
                for (int mf = 0; mf < 2; mf++) {
                    mma_tf32(acc[mf][2 * nf2],     a[mf], t[0], t[2]);
                    mma_tf32(acc[mf][2 * nf2 + 1], a[mf], t[1], t[3]);
                }
            }
        }

        {   // read stage c%3 -> (c+1)%3
            const int rd = ((c % 3) == 2) ? -2 * STAGE : STAGE;
            rdA[0] += rd; rdA[1] += rd;
#pragma unroll
            for (int i = 0; i < 4; i++) rdB[i] += rd;
        }
    }

    // epilogue: bias + GELU + dot(w2) -> atomicAdd logit[row]
    __syncthreads();
    const int r4 = lane >> 2, c2 = (lane & 3) * 2;
    float2 bs[8], ws[8];
#pragma unroll
    for (int nf = 0; nf < 8; nf++) {
        bs[nf] = *(const float2*)&bias[col0 + wn * 64 + nf * 8 + c2];
        ws[nf] = *(const float2*)&w2[col0 + wn * 64 + nf * 8 + c2];
    }
#pragma unroll
    for (int mf = 0; mf < 2; mf++)
#pragma unroll
        for (int h = 0; h < 2; h++) {
            float s = 0.f;
#pragma unroll
            for (int nf = 0; nf < 8; nf++) {
                float v0 = acc[mf][nf][2 * h]     + bs[nf].x;
                float v1 = acc[mf][nf][2 * h + 1] + bs[nf].y;
                v0 = 0.5f * v0 * (1.0f + erff(v0 * 0.70710678118654752f));
                v1 = 0.5f * v1 * (1.0f + erff(v1 * 0.70710678118654752f));
                s += v0 * ws[nf].x + v1 * ws[nf].y;
            }
            s += __shfl_xor_sync(0xffffffffu, s, 1);
            s += __shfl_xor_sync(0xffffffffu, s, 2);
            if ((lane & 3) == 0) {
                int row = row0 + wm * 32 + mf * 16 + h * 8 + r4;
                atomicAdd(&logit[row], s);
            }
        }
}

// -------- fused fractional shift + causal window context: g_actx from g_a -------
__global__ void ctx_kernel(const float* __restrict__ theta)
{
    const int t = blockIdx.x;
    const int b = blockIdx.y;
    const int d = threadIdx.x;

    float th    = fminf(fmaxf(theta[0], -12.f), 12.f);
    float delta = 2.0f + 4.0f / (1.0f + expf(-th));
    float dl    = fminf(fmaxf(delta, 0.f), (float)(T_ - 1));
    float nf    = floorf(dl);
    float alpha = dl - nf;
    int   ni    = (int)nf;

    float center = fminf(fmaxf((float)t + delta, 0.f), (float)t);
    int lo = max(0, (int)floorf(center - 5.0f) - 1);
    int hi = min(t, (int)ceilf (center + 5.0f) + 1);

    const float* ab = g_a + (size_t)b * T_ * DM_;
    float sum = 0.f; int cnt = 0;
    for (int tau = lo; tau <= hi; tau++) {
        if (fabsf((float)tau - center) <= 5.0f) {
            cnt++;
            int i0 = min(max(tau - ni, 0), T_ - 1);
            int i1 = min(i0 + 1, T_ - 1);
            sum += (1.0f - alpha) * ab[i0 * DM_ + d] + alpha * ab[i1 * DM_ + d];
        }
    }
    g_actx[((size_t)b * T_ + t) * DM_ + d] = sum / fmaxf((float)cnt, 1e-8f);
}

// -- build X = [an, vn, an*vn] tf32-rounded, with L2 normalization (warp/row) ----
__global__ void buildx_kernel()
{
    const int row  = blockIdx.x * 8 + (threadIdx.x >> 5);
    const int lane = threadIdx.x & 31;
    const float* v  = g_v    + (size_t)row * DM_;
    const float* ac = g_actx + (size_t)row * DM_;

    float vv[8], aa[8];
    float sv = 0.f, sa = 0.f;
#pragma unroll
    for (int i = 0; i < 8; i++) {
        vv[i] = v[lane + 32 * i];
        aa[i] = ac[lane + 32 * i];
        sv += vv[i] * vv[i];
        sa += aa[i] * aa[i];
    }
#pragma unroll
    for (int o = 16; o > 0; o >>= 1) {
        sv += __shfl_xor_sync(0xffffffffu, sv, o);
        sa += __shfl_xor_sync(0xffffffffu, sa, o);
    }
    float iv = 1.0f / fmaxf(sqrtf(sv), 1e-8f);
    float ia = 1.0f / fmaxf(sqrtf(sa), 1e-8f);

    float* x = g_x + (size_t)row * (3 * DM_);
#pragma unroll
    for (int i = 0; i < 8; i++) {
        int d = lane + 32 * i;
        float an = aa[i] * ia, vn = vv[i] * iv;
        x[d]           = round_tf32(an);
        x[DM_ + d]     = round_tf32(vn);
        x[2 * DM_ + d] = round_tf32(an * vn);
    }
}

// -------- gate: logit -> sigmoid -> blend: out = g*a_ctx + (1-g)*v --------------
__global__ void gate_kernel(const float* __restrict__ b2, float* __restrict__ out)
{
    const int row = blockIdx.x;
    const int tid = threadIdx.x;
    float logitv = fminf(fmaxf(g_logit[row] + b2[0], -12.f), 12.f);
    float g = 1.0f / (1.0f + expf(-logitv));
    g = fminf(fmaxf(g, 0.05f), 0.95f);
    float ac = g_actx[(size_t)row * DM_ + tid];
    float v  = g_v  [(size_t)row * DM_ + tid];
    out[(size_t)row * DM_ + tid] = g * ac + (1.0f - g) * v;
}

// --------------------------------- launcher ------------------------------------
extern "C" void kernel_launch(void* const* d_in, const int* in_sizes, int n_in,
                              void* d_out, int out_size)
{
    const float* video = (const float*)d_in[0];
    const float* audio = (const float*)d_in[1];
    const float* Wv    = (const float*)d_in[2];
    const float* bv    = (const float*)d_in[3];
    const float* Wa    = (const float*)d_in[4];
    const float* ba    = (const float*)d_in[5];
    const float* theta = (const float*)d_in[6];
    const float* W1    = (const float*)d_in[7];
    const float* b1    = (const float*)d_in[8];
    const float* W2    = (const float*)d_in[9];
    const float* b2    = (const float*)d_in[10];
    float* out = (float*)d_out;

    float *pv, *pa, *px, *plog, *wvt, *wat, *w1t;
    cudaGetSymbolAddress((void**)&pv,   g_v);
    cudaGetSymbolAddress((void**)&pa,   g_a);
    cudaGetSymbolAddress((void**)&px,   g_x);
    cudaGetSymbolAddress((void**)&plog, g_logit);
    cudaGetSymbolAddress((void**)&wvt,  g_wvt);
    cudaGetSymbolAddress((void**)&wat,  g_wat);
    cudaGetSymbolAddress((void**)&w1t,  g_w1t);

    const int SMEM_LN  = 4 * 49152 + 128 * 4 * 8;   // 200704
    const int SMEM_MLP = 3 * 32768;                 // 98304
    cudaFuncSetAttribute((const void*)gemm_ln,
                         cudaFuncAttributeMaxDynamicSharedMemorySize, SMEM_LN);
    cudaFuncSetAttribute((const void*)gemm_mlp,
                         cudaFuncAttributeMaxDynamicSharedMemorySize, SMEM_MLP);

    cudaMemsetAsync(plog, 0, ROWS * sizeof(float));

    dim3 wblk(32, 8);
    wprep_kernel<<<dim3(DM_  / 32, 1024 / 32), wblk>>>(Wv, wvt, 1024, DM_);
    wprep_kernel<<<dim3(DM_  / 32,  768 / 32), wblk>>>(Wa, wat,  768, DM_);
    wprep_kernel<<<dim3(HID_ / 32,  768 / 32), wblk>>>(W1, w1t,  768, HID_);

    // v = LN(video @ Wv + bv)   M=16384 K=1024 N=256
    gemm_ln<<<dim3(1, ROWS / 128), dim3(512), SMEM_LN>>>(video, wvt, bv, pv, DM_, 1024);
    // a = LN(audio @ Wa + ba)   M=16384 K=768  N=256
    gemm_ln<<<dim3(1, ROWS / 128), dim3(512), SMEM_LN>>>(audio, wat, ba, pa, DM_, 768);
    // a_ctx
    ctx_kernel<<<dim3(T_, B_), dim3(256)>>>(theta);
    // X = [an, vn, an*vn] (tf32-rounded)
    buildx_kernel<<<ROWS / 8, dim3(256)>>>();
    // logits += gelu(X @ W1 + b1) . W2   (2 CTAs/SM MLP)
    gemm_mlp<<<dim3(HID_ / 128, ROWS / 128), dim3(256), SMEM_MLP>>>(px, w1t, b1,
                                                                    W2, plog, 768);
    // gate + blend
    gate_kernel<<<ROWS, dim3(256)>>>(b2, out);
}